// round 15
// baseline (speedup 1.0000x reference)
#include <cuda_runtime.h>
#include <cuda_fp16.h>
#include <cstdint>
#include <math.h>

#define D_MODEL 1024
#define NH      16
#define DFF     2688
#define BATCH   2
#define SEQL    2048
#define M_ROWS  (BATCH*SEQL)   // 4096

// 0.125 (1/sqrt(64)) * log2(e): folded into Q at qkv-GEMM epilogue
#define QSCALE_LOG2 0.18033688f

// ---------------- scratch (device globals; no allocation APIs) ----------------
__device__ __half g_xnh [(size_t)M_ROWS*D_MODEL];
__device__ __half g_qkvh[(size_t)M_ROWS*3*D_MODEL];
__device__ __half g_attnh[(size_t)M_ROWS*D_MODEL];
__device__ __half g_ffhh[(size_t)M_ROWS*DFF];

#define W_TOTAL (3*D_MODEL*D_MODEL + D_MODEL*D_MODEL + 2*DFF*D_MODEL + D_MODEL*DFF)
__device__ __half g_wh[(size_t)W_TOTAL];

// ---------------- helpers ----------------
__device__ __forceinline__ uint32_t smem_u32(const void* p) {
    uint32_t a;
    asm("{ .reg .u64 t; cvta.to.shared.u64 t, %1; cvt.u32.u64 %0, t; }" : "=r"(a) : "l"(p));
    return a;
}
__device__ __forceinline__ void cp16(uint32_t saddr, const void* g) {
    asm volatile("cp.async.cg.shared.global [%0], [%1], 16;" :: "r"(saddr), "l"(g));
}
__device__ __forceinline__ void cp_commit() {
    asm volatile("cp.async.commit_group;" ::: "memory");
}
__device__ __forceinline__ void cp_wait0() {
    asm volatile("cp.async.wait_group 0;" ::: "memory");
}
__device__ __forceinline__ void cp_wait1() {
    asm volatile("cp.async.wait_group 1;" ::: "memory");
}
__device__ __forceinline__ void ldsm4(uint32_t* r, uint32_t saddr) {
    asm volatile("ldmatrix.sync.aligned.m8n8.x4.shared.b16 {%0,%1,%2,%3}, [%4];"
        : "=r"(r[0]), "=r"(r[1]), "=r"(r[2]), "=r"(r[3]) : "r"(saddr));
}
__device__ __forceinline__ void ldsm4t(uint32_t* r, uint32_t saddr) {
    asm volatile("ldmatrix.sync.aligned.m8n8.x4.trans.shared.b16 {%0,%1,%2,%3}, [%4];"
        : "=r"(r[0]), "=r"(r[1]), "=r"(r[2]), "=r"(r[3]) : "r"(saddr));
}
__device__ __forceinline__ void mma16816(float* c, const uint32_t* a, uint32_t b0, uint32_t b1) {
    asm volatile(
        "mma.sync.aligned.m16n8k16.row.col.f32.f16.f16.f32 "
        "{%0,%1,%2,%3}, {%4,%5,%6,%7}, {%8,%9}, {%0,%1,%2,%3};"
        : "+f"(c[0]), "+f"(c[1]), "+f"(c[2]), "+f"(c[3])
        : "r"(a[0]), "r"(a[1]), "r"(a[2]), "r"(a[3]), "r"(b0), "r"(b1));
}
__device__ __forceinline__ uint32_t pack_h2(float a, float b) {
    __half2 h = __floats2half2_rn(a, b);
    return *(uint32_t*)&h;
}
__device__ __forceinline__ float ex2(float x) {
    float r;
    asm("ex2.approx.f32 %0, %1;" : "=f"(r) : "f"(x));
    return r;
}
// 64B-row swizzle (BK=32 tiles)
__device__ __forceinline__ uint32_t sw_off(int row, int chunk) {
    return (uint32_t)(row * 64 + ((chunk ^ ((row >> 1) & 3)) << 4));
}
// 128B-row swizzle (64-col fp16 tiles)
__device__ __forceinline__ uint32_t sw128(int row, int chunk) {
    return (uint32_t)(row * 128 + ((chunk ^ (row & 7)) << 4));
}
__device__ __forceinline__ float silu_mul(float a, float b) {
    return a * (1.f / (1.f + __expf(-a))) * b;
}

// ---------------- HMMA GEMM: C = A*B^T (+resid) ----------------
// CTA 64x128, 256 threads (8 warps: 2m x 4n), warp tile 32x32, BK=32, 2-stage.
// __launch_bounds__(256,4) caps regs at 64 -> 4 CTAs / 32 warps per SM.
#define GBM 64
#define GBN 128
#define BK 32
#define A_TB 4096
#define B_TB 8192

template<bool OUT_HALF>
__global__ void __launch_bounds__(256, 4) gemm_hmma(
    const __half* __restrict__ A, const __half* __restrict__ B,
    const float* __restrict__ resid, void* __restrict__ Cv,
    int M, int N, int K, float oscale, int oscale_cols)
{
    __shared__ __align__(128) __half As[2][GBM*BK];
    __shared__ __align__(128) __half Bs[2][GBN*BK];

    int tid = threadIdx.x;
    int wid = tid >> 5, lane = tid & 31;
    int wm = wid & 1, wn = wid >> 1;     // 2m x 4n warp grid, 32x32 tiles
    int m0 = blockIdx.y * GBM, n0 = blockIdx.x * GBN;

    uint32_t as_base = smem_u32(As);
    uint32_t bs_base = smem_u32(Bs);

    // A loader: 64 rows x 4 chunks, 1 cp16/thread
    int ar = tid >> 2, ac = tid & 3;
    const char* gA = (const char*)(A + (size_t)(m0 + ar) * K) + ac * 16;
    uint32_t sA = as_base + sw_off(ar, ac);
    // B loader: 128 rows x 4 chunks, 2 cp16/thread
    int br = tid >> 1, bc = (tid & 1) * 2;
    const char* gB = (const char*)(B + (size_t)(n0 + br) * K) + bc * 16;
    uint32_t sB0 = bs_base + sw_off(br, bc);
    uint32_t sB1 = bs_base + sw_off(br, bc + 1);

    int rowsel = ((lane >> 3) & 1) * 8 + (lane & 7);
    int chunk_hi = lane >> 4;

    float acc[2][4][4];
    #pragma unroll
    for (int mt = 0; mt < 2; mt++)
        #pragma unroll
        for (int nt = 0; nt < 4; nt++)
            #pragma unroll
            for (int i = 0; i < 4; i++) acc[mt][nt][i] = 0.f;

    int iters = K / BK;
    cp16(sA, gA);
    cp16(sB0, gB); cp16(sB1, gB + 16);
    cp_commit();
    cp_wait0();
    __syncthreads();

    int buf = 0;
    for (int kb = 0; kb < iters; kb++) {
        if (kb + 1 < iters) {
            size_t go = (size_t)(kb + 1) * 64;
            cp16(sA + (buf ^ 1) * A_TB, gA + go);
            cp16(sB0 + (buf ^ 1) * B_TB, gB + go);
            cp16(sB1 + (buf ^ 1) * B_TB, gB + go + 16);
            cp_commit();
        }
        uint32_t ab = as_base + buf * A_TB;
        uint32_t bb = bs_base + buf * B_TB;
        #pragma unroll
        for (int ks = 0; ks < 2; ks++) {
            int cb = ks * 2 + chunk_hi;
            uint32_t a[2][4];
            #pragma unroll
            for (int mt = 0; mt < 2; mt++)
                ldsm4(a[mt], ab + sw_off(wm * 32 + mt * 16 + rowsel, cb));
            uint32_t b[2][4];
            #pragma unroll
            for (int p = 0; p < 2; p++)
                ldsm4(b[p], bb + sw_off(wn * 32 + p * 16 + rowsel, cb));
            #pragma unroll
            for (int mt = 0; mt < 2; mt++)
                #pragma unroll
                for (int p = 0; p < 2; p++)
                    #pragma unroll
                    for (int q = 0; q < 2; q++)
                        mma16816(acc[mt][p*2+q], a[mt], b[p][q], b[p][2 + q]);
        }
        if (kb + 1 < iters) cp_wait0();
        __syncthreads();
        buf ^= 1;
    }

    int r0 = lane >> 2, c0 = (lane & 3) * 2;
    #pragma unroll
    for (int mt = 0; mt < 2; mt++) {
        #pragma unroll
        for (int nt = 0; nt < 4; nt++) {
            int row = m0 + wm * 32 + mt * 16 + r0;
            int col = n0 + wn * 32 + nt * 8 + c0;
            if (OUT_HALF) {
                float sc = (col < oscale_cols) ? oscale : 1.f;
                __half* C = (__half*)Cv;
                *(uint32_t*)(C + (size_t)row * N + col)       = pack_h2(acc[mt][nt][0]*sc, acc[mt][nt][1]*sc);
                *(uint32_t*)(C + (size_t)(row + 8) * N + col) = pack_h2(acc[mt][nt][2]*sc, acc[mt][nt][3]*sc);
            } else {
                float* C = (float*)Cv;
                float2 v0 = make_float2(acc[mt][nt][0], acc[mt][nt][1]);
                float2 v1 = make_float2(acc[mt][nt][2], acc[mt][nt][3]);
                if (resid) {
                    float2 a0 = *(const float2*)(resid + (size_t)row * N + col);
                    float2 a1 = *(const float2*)(resid + (size_t)(row + 8) * N + col);
                    v0.x += a0.x; v0.y += a0.y; v1.x += a1.x; v1.y += a1.y;
                }
                *(float2*)(C + (size_t)row * N + col)       = v0;
                *(float2*)(C + (size_t)(row + 8) * N + col) = v1;
            }
        }
    }
}

// ---------------- Fused FFN-up (R5-proven): H = silu(A*W1^T)*(A*W3^T) ----------------
#define TILE_B 8192

__global__ void __launch_bounds__(256) gemm_ffup(
    const __half* __restrict__ A, const __half* __restrict__ B1,
    const __half* __restrict__ B2, __half* __restrict__ H,
    int M, int N, int K)
{
    __shared__ __align__(128) __half As [2][128*BK];
    __shared__ __align__(128) __half B1s[2][128*BK];
    __shared__ __align__(128) __half B2s[2][128*BK];

    int tid = threadIdx.x;
    int wid = tid >> 5, lane = tid & 31;
    int wm = wid & 3, wn = wid >> 2;
    int m0 = blockIdx.y * 128, n0 = blockIdx.x * 128;

    uint32_t as_base  = smem_u32(As);
    uint32_t b1_base  = smem_u32(B1s);
    uint32_t b2_base  = smem_u32(B2s);

    int lr = tid >> 1;
    int lc = (tid & 1) * 2;
    const char* gA  = (const char*)(A  + (size_t)(m0 + lr) * K) + lc * 16;
    const char* gB1 = (const char*)(B1 + (size_t)(n0 + lr) * K) + lc * 16;
    const char* gB2 = (const char*)(B2 + (size_t)(n0 + lr) * K) + lc * 16;
    uint32_t so0 = sw_off(lr, lc), so1 = sw_off(lr, lc + 1);

    int rowsel = ((lane >> 3) & 1) * 8 + (lane & 7);
    int chunk_hi = lane >> 4;

    float acc1[2][8][4], acc2[2][8][4];
    #pragma unroll
    for (int mt = 0; mt < 2; mt++)
        #pragma unroll
        for (int nt = 0; nt < 8; nt++)
            #pragma unroll
            for (int i = 0; i < 4; i++) { acc1[mt][nt][i] = 0.f; acc2[mt][nt][i] = 0.f; }

    int iters = K / BK;
    cp16(as_base + so0, gA);  cp16(as_base + so1, gA + 16);
    cp16(b1_base + so0, gB1); cp16(b1_base + so1, gB1 + 16);
    cp16(b2_base + so0, gB2); cp16(b2_base + so1, gB2 + 16);
    cp_commit();
    cp_wait0();
    __syncthreads();

    int buf = 0;
    for (int kb = 0; kb < iters; kb++) {
        if (kb + 1 < iters) {
            size_t go = (size_t)(kb + 1) * 64;
            uint32_t bo = (buf ^ 1) * TILE_B;
            cp16(as_base + bo + so0, gA + go);  cp16(as_base + bo + so1, gA + go + 16);
            cp16(b1_base + bo + so0, gB1 + go); cp16(b1_base + bo + so1, gB1 + go + 16);
            cp16(b2_base + bo + so0, gB2 + go); cp16(b2_base + bo + so1, gB2 + go + 16);
            cp_commit();
        }
        uint32_t ab  = as_base + buf * TILE_B;
        uint32_t bb1 = b1_base + buf * TILE_B;
        uint32_t bb2 = b2_base + buf * TILE_B;
        #pragma unroll
        for (int ks = 0; ks < 2; ks++) {
            int cb = ks * 2 + chunk_hi;
            uint32_t a[2][4];
            #pragma unroll
            for (int mt = 0; mt < 2; mt++)
                ldsm4(a[mt], ab + sw_off(wm * 32 + mt * 16 + rowsel, cb));
            #pragma unroll
            for (int p = 0; p < 4; p++) {
                uint32_t b1[4], b2[4];
                uint32_t ro = sw_off(wn * 64 + p * 16 + rowsel, cb);
                ldsm4(b1, bb1 + ro);
                ldsm4(b2, bb2 + ro);
                #pragma unroll
                for (int mt = 0; mt < 2; mt++)
                    #pragma unroll
                    for (int q = 0; q < 2; q++) {
                        mma16816(acc1[mt][p*2+q], a[mt], b1[q], b1[2 + q]);
                        mma16816(acc2[mt][p*2+q], a[mt], b2[q], b2[2 + q]);
                    }
            }
        }
        if (kb + 1 < iters) cp_wait0();
        __syncthreads();
        buf ^= 1;
    }

    const int r0 = lane >> 2, c0 = (lane & 3) * 2;
    #pragma unroll
    for (int mt = 0; mt < 2; mt++) {
        #pragma unroll
        for (int nt = 0; nt < 8; nt++) {
            int row = m0 + wm * 32 + mt * 16 + r0;
            int col = n0 + wn * 64 + nt * 8 + c0;
            float h0 = silu_mul(acc1[mt][nt][0], acc2[mt][nt][0]);
            float h1 = silu_mul(acc1[mt][nt][1], acc2[mt][nt][1]);
            float h2 = silu_mul(acc1[mt][nt][2], acc2[mt][nt][2]);
            float h3 = silu_mul(acc1[mt][nt][3], acc2[mt][nt][3]);
            *(uint32_t*)(H + (size_t)row * N + col)       = pack_h2(h0, h1);
            *(uint32_t*)(H + (size_t)(row + 8) * N + col) = pack_h2(h2, h3);
        }
    }
}

// ---------------- HMMA flash attention (log2-domain softmax; Q pre-scaled) ----------------
__global__ void __launch_bounds__(256) attn_hmma(const __half* __restrict__ qkv,
                                                 __half* __restrict__ out) {
    __shared__ __align__(128) __half Qs[128*64];
    __shared__ __align__(128) __half Ks[2][64*64];
    __shared__ __align__(128) __half Vs[2][64*64];
    const int tid = threadIdx.x, lane = tid & 31, wid = tid >> 5;
    const int b = blockIdx.y >> 4, h = blockIdx.y & 15;
    const int q0 = ((int)gridDim.x - 1 - (int)blockIdx.x) * 128;
    const __half* base = qkv + (size_t)b * SEQL * (3*D_MODEL) + h * 64;

    uint32_t qs  = smem_u32(Qs);
    uint32_t ksm = smem_u32(Ks);
    uint32_t vsm = smem_u32(Vs);

    {
        int r = tid >> 1, c0 = (tid & 1) * 4;
        const char* g = (const char*)(base + (size_t)(q0 + r) * (3*D_MODEL));
        #pragma unroll
        for (int c = 0; c < 4; c++) {
            int ch = c0 + c;
            cp16(qs + sw128(r, ch), g + ch * 16);
        }
    }
    const int T = q0 / 64 + 2;

    {
        int r = tid >> 2, c0 = (tid & 3) * 2;
        const char* gk = (const char*)(base + 1024 + (size_t)r * (3*D_MODEL));
        const char* gv = (const char*)(base + 2048 + (size_t)r * (3*D_MODEL));
        #pragma unroll
        for (int c = 0; c < 2; c++) {
            int ch = c0 + c;
            uint32_t sw = sw128(r, ch);
            cp16(ksm + sw, gk + ch * 16);
            cp16(vsm + sw, gv + ch * 16);
        }
    }
    cp_commit();
    cp_wait0();
    __syncthreads();

    uint32_t aq[4][4];
    {
        int row = wid * 16 + (lane & 15);
        #pragma unroll
        for (int ks = 0; ks < 4; ks++) {
            int ch = 2 * ks + (lane >> 4);
            ldsm4(aq[ks], qs + sw128(row, ch));
        }
    }

    float acc_o[8][4];
    #pragma unroll
    for (int j = 0; j < 8; j++)
        #pragma unroll
        for (int i = 0; i < 4; i++) acc_o[j][i] = 0.f;
    float m_lo = -1e30f, m_hi = -1e30f, l_lo = 0.f, l_hi = 0.f;

    for (int t = 0; t < T; t++) {
        int buf = t & 1;
        if (t + 1 < T) {
            int r = tid >> 2, c0 = (tid & 3) * 2;
            const char* gk = (const char*)(base + 1024 + (size_t)((t+1)*64 + r) * (3*D_MODEL));
            const char* gv = (const char*)(base + 2048 + (size_t)((t+1)*64 + r) * (3*D_MODEL));
            uint32_t so = (uint32_t)(buf ^ 1) * 8192;
            #pragma unroll
            for (int c = 0; c < 2; c++) {
                int ch = c0 + c;
                uint32_t sw = so + sw128(r, ch);
                cp16(ksm + sw, gk + ch * 16);
                cp16(vsm + sw, gv + ch * 16);
            }
            cp_commit();
            cp_wait1();
        } else {
            cp_wait0();
        }
        __syncthreads();

        uint32_t kb = ksm + buf * 8192;
        uint32_t vb = vsm + buf * 8192;

        float s[8][4];
        #pragma unroll
        for (int j = 0; j < 8; j++)
            #pragma unroll
            for (int i = 0; i < 4; i++) s[j][i] = 0.f;
        #pragma unroll
        for (int ks = 0; ks < 4; ks++) {
            #pragma unroll
            for (int j = 0; j < 8; j += 2) {
                int row = j * 8 + ((lane >> 4) << 3) + (lane & 7);
                int ch = 2 * ks + ((lane >> 3) & 1);
                uint32_t bk[4];
                ldsm4(bk, kb + sw128(row, ch));
                mma16816(s[j],     aq[ks], bk[0], bk[1]);
                mma16816(s[j + 1], aq[ks], bk[2], bk[3]);
            }
        }

        float mx_lo = -1e30f, mx_hi = -1e30f;
        if (t >= T - 2) {
            int q_lo = q0 + wid * 16 + (lane >> 2);
            int kvb  = t * 64 + (lane & 3) * 2;
            #pragma unroll
            for (int j = 0; j < 8; j++) {
                #pragma unroll
                for (int c = 0; c < 4; c++) {
                    int kv = kvb + j * 8 + (c & 1);
                    int qr = q_lo + ((c >= 2) ? 8 : 0);
                    if (kv > qr) s[j][c] = -1e30f;
                }
                mx_lo = fmaxf(mx_lo, fmaxf(s[j][0], s[j][1]));
                mx_hi = fmaxf(mx_hi, fmaxf(s[j][2], s[j][3]));
            }
        } else {
            #pragma unroll
            for (int j = 0; j < 8; j++) {
                mx_lo = fmaxf(mx_lo, fmaxf(s[j][0], s[j][1]));
                mx_hi = fmaxf(mx_hi, fmaxf(s[j][2], s[j][3]));
            }
        }
        mx_lo = fmaxf(mx_lo, __shfl_xor_sync(0xffffffffu, mx_lo, 1));
        mx_lo = fmaxf(mx_lo, __shfl_xor_sync(0xffffffffu, mx_lo, 2));
        mx_hi = fmaxf(mx_hi, __shfl_xor_sync(0xffffffffu, mx_hi, 1));
        mx_hi = fmaxf(mx_hi, __shfl_xor_sync(0xffffffffu, mx_hi, 2));

        float mn_lo = fmaxf(m_lo, mx_lo), mn_hi = fmaxf(m_hi, mx_hi);
        float cr_lo = ex2(m_lo - mn_lo), cr_hi = ex2(m_hi - mn_hi);
        m_lo = mn_lo; m_hi = mn_hi;

        float pl = 0.f, ph = 0.f;
        #pragma unroll
        for (int j = 0; j < 8; j++) {
            s[j][0] = ex2(s[j][0] - mn_lo); pl += s[j][0];
            s[j][1] = ex2(s[j][1] - mn_lo); pl += s[j][1];
            s[j][2] = ex2(s[j][2] - mn_hi); ph += s[j][2];
            s[j][3] = ex2(s[j][3] - mn_hi); ph += s[j][3];
        }
        pl += __shfl_xor_sync(0xffffffffu, pl, 1);
        pl += __shfl_xor_sync(0xffffffffu, pl, 2);
        ph += __shfl_xor_sync(0xffffffffu, ph, 1);
        ph += __shfl_xor_sync(0xffffffffu, ph, 2);
        l_lo = l_lo * cr_lo + pl;
        l_hi = l_hi * cr_hi + ph;

        #pragma unroll
        for (int j = 0; j < 8; j++) {
            acc_o[j][0] *= cr_lo; acc_o[j][1] *= cr_lo;
            acc_o[j][2] *= cr_hi; acc_o[j][3] *= cr_hi;
        }

        uint32_t ap[4][4];
        #pragma unroll
        for (int c16 = 0; c16 < 4; c16++) {
            ap[c16][0] = pack_h2(s[2*c16][0],   s[2*c16][1]);
            ap[c16][1] = pack_h2(s[2*c16][2],   s[2*c16][3]);
            ap[c16][2] = pack_h2(s[2*c16+1][0], s[2*c16+1][1]);
            ap[c16][3] = pack_h2(s[2*c16+1][2], s[2*c16+1][3]);
        }

        #pragma unroll
        for (int c16 = 0; c16 < 4; c16++) {
            int row = c16 * 16 + (lane & 15);
            #pragma unroll
            for (int j = 0; j < 8; j += 2) {
                int ch = j + (lane >> 4);
                uint32_t bv[4];
                ldsm4t(bv, vb + sw128(row, ch));
                mma16816(acc_o[j],     ap[c16], bv[0], bv[1]);
                mma16816(acc_o[j + 1], ap[c16], bv[2], bv[3]);
            }
        }
        __syncthreads();
    }

    float il_lo = 1.f / l_lo, il_hi = 1.f / l_hi;
    int r = lane >> 2, c = (lane & 3) * 2;
    __half* o_lo = out + (size_t)((b*SEQL) + q0 + wid*16 + r) * D_MODEL + h * 64 + c;
    __half* o_hi = o_lo + (size_t)8 * D_MODEL;
    #pragma unroll
    for (int j = 0; j < 8; j++) {
        *(uint32_t*)(o_lo + j*8) = pack_h2(acc_o[j][0]*il_lo, acc_o[j][1]*il_lo);
        *(uint32_t*)(o_hi + j*8) = pack_h2(acc_o[j][2]*il_hi, acc_o[j][3]*il_hi);
    }
}

// ---------------- weight converts ----------------
__global__ void f2h_one(const float* __restrict__ x, __half* __restrict__ y, int n4) {
    int i = blockIdx.x * blockDim.x + threadIdx.x;
    if (i < n4) {
        float4 v = ((const float4*)x)[i];
        ((uint2*)y)[i] = make_uint2(pack_h2(v.x, v.y), pack_h2(v.z, v.w));
    }
}

__global__ void f2h_rest(const float* __restrict__ wo, const float* __restrict__ w1,
                         const float* __restrict__ w3, const float* __restrict__ w2,
                         __half* __restrict__ y) {   // y = wh + o_wo
    const int n0 = D_MODEL*D_MODEL/4;
    const int n1 = n0 + DFF*D_MODEL/4;
    const int n2 = n1 + DFF*D_MODEL/4;
    const int n3 = n2 + D_MODEL*DFF/4;
    int i = blockIdx.x * blockDim.x + threadIdx.x;
    if (i >= n3) return;
    const float* src;
    int base;
    if      (i < n0) { src = wo; base = 0;  }
    else if (i < n1) { src = w1; base = n0; }
    else if (i < n2) { src = w3; base = n1; }
    else             { src = w2; base = n2; }
    float4 v = ((const float4*)src)[i - base];
    ((uint2*)y)[i] = make_uint2(pack_h2(v.x, v.y), pack_h2(v.z, v.w));
}

// ---------------- RMSNorm -> fp16 ----------------
__global__ void rmsnorm_k(const float* __restrict__ x, const float* __restrict__ g,
                          __half* __restrict__ out) {
    int row = blockIdx.x;
    const float4* x4 = (const float4*)(x + (size_t)row * D_MODEL);
    const float4* g4 = (const float4*)g;
    float4 v = x4[threadIdx.x];
    float ss = v.x*v.x + v.y*v.y + v.z*v.z + v.w*v.w;
    #pragma unroll
    for (int o = 16; o; o >>= 1) ss += __shfl_xor_sync(0xffffffffu, ss, o);
    __shared__ float wsum[8];
    int w = threadIdx.x >> 5, l = threadIdx.x & 31;
    if (l == 0) wsum[w] = ss;
    __syncthreads();
    if (w == 0) {
        float t = (l < 8) ? wsum[l] : 0.f;
        #pragma unroll
        for (int o = 4; o; o >>= 1) t += __shfl_xor_sync(0xffffffffu, t, o);
        if (l == 0) wsum[0] = t;
    }
    __syncthreads();
    float inv = rsqrtf(wsum[0] * (1.0f / (float)D_MODEL) + 1e-5f);
    float4 gg = g4[threadIdx.x];
    ((uint2*)(out + (size_t)row * D_MODEL))[threadIdx.x] =
        make_uint2(pack_h2(v.x*gg.x*inv, v.y*gg.y*inv), pack_h2(v.z*gg.z*inv, v.w*gg.w*inv));
}

// ---------------- launch ----------------
extern "C" void kernel_launch(void* const* d_in, const int* in_sizes, int n_in,
                              void* d_out, int out_size) {
    const float* x    = (const float*)d_in[0];
    const float* wqkv = (const float*)d_in[1];
    const float* wo   = (const float*)d_in[2];
    const float* g1   = (const float*)d_in[3];
    const float* g2   = (const float*)d_in[4];
    const float* w1   = (const float*)d_in[5];
    const float* w2   = (const float*)d_in[6];
    const float* w3   = (const float*)d_in[7];
    float* out = (float*)d_out;

    __half *xnh, *qkvh, *attnh, *ffhh, *wh;
    cudaGetSymbolAddress((void**)&xnh,   g_xnh);
    cudaGetSymbolAddress((void**)&qkvh,  g_qkvh);
    cudaGetSymbolAddress((void**)&attnh, g_attnh);
    cudaGetSymbolAddress((void**)&ffhh,  g_ffhh);
    cudaGetSymbolAddress((void**)&wh,    g_wh);

    size_t o_qkv = 0;
    size_t o_wo  = o_qkv + (size_t)3*D_MODEL*D_MODEL;
    size_t o_w1  = o_wo  + (size_t)D_MODEL*D_MODEL;
    size_t o_w3  = o_w1  + (size_t)DFF*D_MODEL;
    size_t o_w2  = o_w3  + (size_t)DFF*D_MODEL;

    // side stream: convert wo/w1/w3/w2 concurrently with the attention phase
    cudaStream_t s2;
    cudaStreamCreate(&s2);
    cudaEvent_t eFork, eW;
    cudaEventCreateWithFlags(&eFork, cudaEventDisableTiming);
    cudaEventCreateWithFlags(&eW,    cudaEventDisableTiming);

    cudaEventRecord(eFork, 0);
    cudaStreamWaitEvent(s2, eFork, 0);
    {
        int nr4 = (D_MODEL*D_MODEL + 2*DFF*D_MODEL + D_MODEL*DFF) / 4;
        f2h_rest<<<(nr4 + 255)/256, 256, 0, s2>>>(wo, w1, w3, w2, wh + o_wo);
    }
    cudaEventRecord(eW, s2);

    // main stream: wqkv convert -> rms -> qkv GEMM -> attention
    int nq4 = 3*D_MODEL*D_MODEL/4;
    f2h_one<<<(nq4 + 255)/256, 256>>>(wqkv, wh + o_qkv, nq4);
    rmsnorm_k<<<M_ROWS, 256>>>(x, g1, xnh);
    gemm_hmma<true><<<dim3(3*D_MODEL/GBN, M_ROWS/GBM), 256>>>(
        xnh, wh + o_qkv, nullptr, qkvh, M_ROWS, 3*D_MODEL, D_MODEL,
        QSCALE_LOG2, D_MODEL);
    attn_hmma<<<dim3(SEQL/128, BATCH*NH), 256>>>(qkvh, attnh);

    // join: remaining weights must be converted before the wo GEMM
    cudaStreamWaitEvent(0, eW, 0);
    gemm_hmma<false><<<dim3(D_MODEL/GBN, M_ROWS/GBM), 256>>>(
        attnh, wh + o_wo, x, out, M_ROWS, D_MODEL, D_MODEL, 1.f, 0);

    // out += W2 * swiglu(rmsnorm(out,g2))
    rmsnorm_k<<<M_ROWS, 256>>>(out, g2, xnh);
    gemm_ffup<<<dim3(DFF/128, M_ROWS/128), 256>>>(
        xnh, wh + o_w1, wh + o_w3, ffhh, M_ROWS, DFF, D_MODEL);
    gemm_hmma<false><<<dim3(D_MODEL/GBN, M_ROWS/GBM), 256>>>(
        ffhh, wh + o_w2, out, out, M_ROWS, D_MODEL, DFF, 1.f, 0);
}

// round 16
// speedup vs baseline: 1.0713x; 1.0713x over previous
#include <cuda_runtime.h>
#include <cuda_fp16.h>
#include <cstdint>
#include <math.h>

#define D_MODEL 1024
#define NH      16
#define DFF     2688
#define BATCH   2
#define SEQL    2048
#define M_ROWS  (BATCH*SEQL)   // 4096

// 0.125 (1/sqrt(64)) * log2(e): folded into Q at qkv-GEMM epilogue
#define QSCALE_LOG2 0.18033688f

// ---------------- scratch (device globals; no allocation APIs) ----------------
__device__ __half g_xnh [(size_t)M_ROWS*D_MODEL];
__device__ __half g_qkvh[(size_t)M_ROWS*3*D_MODEL];
__device__ __half g_attnh[(size_t)M_ROWS*D_MODEL];
__device__ __half g_ffhh[(size_t)M_ROWS*DFF];

#define W_TOTAL (3*D_MODEL*D_MODEL + D_MODEL*D_MODEL + 2*DFF*D_MODEL + D_MODEL*DFF)
__device__ __half g_wh[(size_t)W_TOTAL];

// ---------------- helpers ----------------
__device__ __forceinline__ uint32_t smem_u32(const void* p) {
    uint32_t a;
    asm("{ .reg .u64 t; cvta.to.shared.u64 t, %1; cvt.u32.u64 %0, t; }" : "=r"(a) : "l"(p));
    return a;
}
__device__ __forceinline__ void cp16(uint32_t saddr, const void* g) {
    asm volatile("cp.async.cg.shared.global [%0], [%1], 16;" :: "r"(saddr), "l"(g));
}
__device__ __forceinline__ void cp_commit() {
    asm volatile("cp.async.commit_group;" ::: "memory");
}
__device__ __forceinline__ void cp_wait0() {
    asm volatile("cp.async.wait_group 0;" ::: "memory");
}
__device__ __forceinline__ void cp_wait1() {
    asm volatile("cp.async.wait_group 1;" ::: "memory");
}
__device__ __forceinline__ void ldsm4(uint32_t* r, uint32_t saddr) {
    asm volatile("ldmatrix.sync.aligned.m8n8.x4.shared.b16 {%0,%1,%2,%3}, [%4];"
        : "=r"(r[0]), "=r"(r[1]), "=r"(r[2]), "=r"(r[3]) : "r"(saddr));
}
__device__ __forceinline__ void ldsm4t(uint32_t* r, uint32_t saddr) {
    asm volatile("ldmatrix.sync.aligned.m8n8.x4.trans.shared.b16 {%0,%1,%2,%3}, [%4];"
        : "=r"(r[0]), "=r"(r[1]), "=r"(r[2]), "=r"(r[3]) : "r"(saddr));
}
__device__ __forceinline__ void mma16816(float* c, const uint32_t* a, uint32_t b0, uint32_t b1) {
    asm volatile(
        "mma.sync.aligned.m16n8k16.row.col.f32.f16.f16.f32 "
        "{%0,%1,%2,%3}, {%4,%5,%6,%7}, {%8,%9}, {%0,%1,%2,%3};"
        : "+f"(c[0]), "+f"(c[1]), "+f"(c[2]), "+f"(c[3])
        : "r"(a[0]), "r"(a[1]), "r"(a[2]), "r"(a[3]), "r"(b0), "r"(b1));
}
__device__ __forceinline__ uint32_t pack_h2(float a, float b) {
    __half2 h = __floats2half2_rn(a, b);
    return *(uint32_t*)&h;
}
__device__ __forceinline__ float ex2(float x) {
    float r;
    asm("ex2.approx.f32 %0, %1;" : "=f"(r) : "f"(x));
    return r;
}
// 64B-row swizzle (BK=32 tiles)
__device__ __forceinline__ uint32_t sw_off(int row, int chunk) {
    return (uint32_t)(row * 64 + ((chunk ^ ((row >> 1) & 3)) << 4));
}
// 128B-row swizzle (64-col fp16 tiles)
__device__ __forceinline__ uint32_t sw128(int row, int chunk) {
    return (uint32_t)(row * 128 + ((chunk ^ (row & 7)) << 4));
}
__device__ __forceinline__ float silu_mul(float a, float b) {
    return a * (1.f / (1.f + __expf(-a))) * b;
}

// ---------------- HMMA GEMM (R14-proven): C = A*B^T (+resid) ----------------
// CTA 64x128, 256 threads (8 warps: 2m x 4n), warp tile 32x32, BK=32, 2-stage.
// __launch_bounds__(256,3) -> ~78 regs, 3 CTAs / 24 warps per SM (measured best).
#define GBM 64
#define GBN 128
#define BK 32
#define A_TB 4096
#define B_TB 8192

template<bool OUT_HALF>
__global__ void __launch_bounds__(256, 3) gemm_hmma(
    const __half* __restrict__ A, const __half* __restrict__ B,
    const float* __restrict__ resid, void* __restrict__ Cv,
    int M, int N, int K, float oscale, int oscale_cols)
{
    __shared__ __align__(128) __half As[2][GBM*BK];
    __shared__ __align__(128) __half Bs[2][GBN*BK];

    int tid = threadIdx.x;
    int wid = tid >> 5, lane = tid & 31;
    int wm = wid & 1, wn = wid >> 1;
    int m0 = blockIdx.y * GBM, n0 = blockIdx.x * GBN;

    uint32_t as_base = smem_u32(As);
    uint32_t bs_base = smem_u32(Bs);

    int ar = tid >> 2, ac = tid & 3;
    const char* gA = (const char*)(A + (size_t)(m0 + ar) * K) + ac * 16;
    uint32_t sA = as_base + sw_off(ar, ac);
    int br = tid >> 1, bc = (tid & 1) * 2;
    const char* gB = (const char*)(B + (size_t)(n0 + br) * K) + bc * 16;
    uint32_t sB0 = bs_base + sw_off(br, bc);
    uint32_t sB1 = bs_base + sw_off(br, bc + 1);

    int rowsel = ((lane >> 3) & 1) * 8 + (lane & 7);
    int chunk_hi = lane >> 4;

    float acc[2][4][4];
    #pragma unroll
    for (int mt = 0; mt < 2; mt++)
        #pragma unroll
        for (int nt = 0; nt < 4; nt++)
            #pragma unroll
            for (int i = 0; i < 4; i++) acc[mt][nt][i] = 0.f;

    int iters = K / BK;
    cp16(sA, gA);
    cp16(sB0, gB); cp16(sB1, gB + 16);
    cp_commit();
    cp_wait0();
    __syncthreads();

    int buf = 0;
    for (int kb = 0; kb < iters; kb++) {
        if (kb + 1 < iters) {
            size_t go = (size_t)(kb + 1) * 64;
            cp16(sA + (buf ^ 1) * A_TB, gA + go);
            cp16(sB0 + (buf ^ 1) * B_TB, gB + go);
            cp16(sB1 + (buf ^ 1) * B_TB, gB + go + 16);
            cp_commit();
        }
        uint32_t ab = as_base + buf * A_TB;
        uint32_t bb = bs_base + buf * B_TB;
        #pragma unroll
        for (int ks = 0; ks < 2; ks++) {
            int cb = ks * 2 + chunk_hi;
            uint32_t a[2][4];
            #pragma unroll
            for (int mt = 0; mt < 2; mt++)
                ldsm4(a[mt], ab + sw_off(wm * 32 + mt * 16 + rowsel, cb));
            uint32_t b[2][4];
            #pragma unroll
            for (int p = 0; p < 2; p++)
                ldsm4(b[p], bb + sw_off(wn * 32 + p * 16 + rowsel, cb));
            #pragma unroll
            for (int mt = 0; mt < 2; mt++)
                #pragma unroll
                for (int p = 0; p < 2; p++)
                    #pragma unroll
                    for (int q = 0; q < 2; q++)
                        mma16816(acc[mt][p*2+q], a[mt], b[p][q], b[p][2 + q]);
        }
        if (kb + 1 < iters) cp_wait0();
        __syncthreads();
        buf ^= 1;
    }

    int r0 = lane >> 2, c0 = (lane & 3) * 2;
    #pragma unroll
    for (int mt = 0; mt < 2; mt++) {
        #pragma unroll
        for (int nt = 0; nt < 4; nt++) {
            int row = m0 + wm * 32 + mt * 16 + r0;
            int col = n0 + wn * 32 + nt * 8 + c0;
            if (OUT_HALF) {
                float sc = (col < oscale_cols) ? oscale : 1.f;
                __half* C = (__half*)Cv;
                *(uint32_t*)(C + (size_t)row * N + col)       = pack_h2(acc[mt][nt][0]*sc, acc[mt][nt][1]*sc);
                *(uint32_t*)(C + (size_t)(row + 8) * N + col) = pack_h2(acc[mt][nt][2]*sc, acc[mt][nt][3]*sc);
            } else {
                float* C = (float*)Cv;
                float2 v0 = make_float2(acc[mt][nt][0], acc[mt][nt][1]);
                float2 v1 = make_float2(acc[mt][nt][2], acc[mt][nt][3]);
                if (resid) {
                    float2 a0 = *(const float2*)(resid + (size_t)row * N + col);
                    float2 a1 = *(const float2*)(resid + (size_t)(row + 8) * N + col);
                    v0.x += a0.x; v0.y += a0.y; v1.x += a1.x; v1.y += a1.y;
                }
                *(float2*)(C + (size_t)row * N + col)       = v0;
                *(float2*)(C + (size_t)(row + 8) * N + col) = v1;
            }
        }
    }
}

// ---------------- Fused FFN-up: H = silu(A*W1^T)*(A*W3^T) ----------------
// Register-light rework: CTA 64x128, 8 warps (2m x 4n), dual 32x32 warp tiles,
// BK=32, 2-stage. ~110 regs -> 2 CTAs / 16 warps per SM (vs 1 CTA before).
__global__ void __launch_bounds__(256, 2) gemm_ffup(
    const __half* __restrict__ A, const __half* __restrict__ B1,
    const __half* __restrict__ B2, __half* __restrict__ H,
    int M, int N, int K)
{
    __shared__ __align__(128) __half As [2][GBM*BK];
    __shared__ __align__(128) __half B1s[2][GBN*BK];
    __shared__ __align__(128) __half B2s[2][GBN*BK];

    int tid = threadIdx.x;
    int wid = tid >> 5, lane = tid & 31;
    int wm = wid & 1, wn = wid >> 1;
    int m0 = blockIdx.y * GBM, n0 = blockIdx.x * GBN;

    uint32_t as_base = smem_u32(As);
    uint32_t b1_base = smem_u32(B1s);
    uint32_t b2_base = smem_u32(B2s);

    int ar = tid >> 2, ac = tid & 3;
    const char* gA = (const char*)(A + (size_t)(m0 + ar) * K) + ac * 16;
    uint32_t sA = as_base + sw_off(ar, ac);
    int br = tid >> 1, bc = (tid & 1) * 2;
    const char* gB1 = (const char*)(B1 + (size_t)(n0 + br) * K) + bc * 16;
    const char* gB2 = (const char*)(B2 + (size_t)(n0 + br) * K) + bc * 16;
    uint32_t so0 = sw_off(br, bc), so1 = sw_off(br, bc + 1);

    int rowsel = ((lane >> 3) & 1) * 8 + (lane & 7);
    int chunk_hi = lane >> 4;

    float acc1[2][4][4], acc2[2][4][4];
    #pragma unroll
    for (int mt = 0; mt < 2; mt++)
        #pragma unroll
        for (int nt = 0; nt < 4; nt++)
            #pragma unroll
            for (int i = 0; i < 4; i++) { acc1[mt][nt][i] = 0.f; acc2[mt][nt][i] = 0.f; }

    int iters = K / BK;
    cp16(sA, gA);
    cp16(b1_base + so0, gB1); cp16(b1_base + so1, gB1 + 16);
    cp16(b2_base + so0, gB2); cp16(b2_base + so1, gB2 + 16);
    cp_commit();
    cp_wait0();
    __syncthreads();

    int buf = 0;
    for (int kb = 0; kb < iters; kb++) {
        if (kb + 1 < iters) {
            size_t go = (size_t)(kb + 1) * 64;
            cp16(sA + (buf ^ 1) * A_TB, gA + go);
            uint32_t bo = (buf ^ 1) * B_TB;
            cp16(b1_base + bo + so0, gB1 + go); cp16(b1_base + bo + so1, gB1 + go + 16);
            cp16(b2_base + bo + so0, gB2 + go); cp16(b2_base + bo + so1, gB2 + go + 16);
            cp_commit();
        }
        uint32_t ab  = as_base + buf * A_TB;
        uint32_t bb1 = b1_base + buf * B_TB;
        uint32_t bb2 = b2_base + buf * B_TB;
        #pragma unroll
        for (int ks = 0; ks < 2; ks++) {
            int cb = ks * 2 + chunk_hi;
            uint32_t a[2][4];
            #pragma unroll
            for (int mt = 0; mt < 2; mt++)
                ldsm4(a[mt], ab + sw_off(wm * 32 + mt * 16 + rowsel, cb));
            #pragma unroll
            for (int p = 0; p < 2; p++) {
                uint32_t b1[4], b2[4];
                uint32_t ro = sw_off(wn * 32 + p * 16 + rowsel, cb);
                ldsm4(b1, bb1 + ro);
                ldsm4(b2, bb2 + ro);
                #pragma unroll
                for (int mt = 0; mt < 2; mt++)
                    #pragma unroll
                    for (int q = 0; q < 2; q++) {
                        mma16816(acc1[mt][p*2+q], a[mt], b1[q], b1[2 + q]);
                        mma16816(acc2[mt][p*2+q], a[mt], b2[q], b2[2 + q]);
                    }
            }
        }
        if (kb + 1 < iters) cp_wait0();
        __syncthreads();
        buf ^= 1;
    }

    const int r0 = lane >> 2, c0 = (lane & 3) * 2;
    #pragma unroll
    for (int mt = 0; mt < 2; mt++) {
        #pragma unroll
        for (int nt = 0; nt < 4; nt++) {
            int row = m0 + wm * 32 + mt * 16 + r0;
            int col = n0 + wn * 32 + nt * 8 + c0;
            float h0 = silu_mul(acc1[mt][nt][0], acc2[mt][nt][0]);
            float h1 = silu_mul(acc1[mt][nt][1], acc2[mt][nt][1]);
            float h2 = silu_mul(acc1[mt][nt][2], acc2[mt][nt][2]);
            float h3 = silu_mul(acc1[mt][nt][3], acc2[mt][nt][3]);
            *(uint32_t*)(H + (size_t)row * N + col)       = pack_h2(h0, h1);
            *(uint32_t*)(H + (size_t)(row + 8) * N + col) = pack_h2(h2, h3);
        }
    }
}

// ---------------- HMMA flash attention (log2-domain softmax; Q pre-scaled) ----------------
__global__ void __launch_bounds__(256) attn_hmma(const __half* __restrict__ qkv,
                                                 __half* __restrict__ out) {
    __shared__ __align__(128) __half Qs[128*64];
    __shared__ __align__(128) __half Ks[2][64*64];
    __shared__ __align__(128) __half Vs[2][64*64];
    const int tid = threadIdx.x, lane = tid & 31, wid = tid >> 5;
    const int b = blockIdx.y >> 4, h = blockIdx.y & 15;
    const int q0 = ((int)gridDim.x - 1 - (int)blockIdx.x) * 128;
    const __half* base = qkv + (size_t)b * SEQL * (3*D_MODEL) + h * 64;

    uint32_t qs  = smem_u32(Qs);
    uint32_t ksm = smem_u32(Ks);
    uint32_t vsm = smem_u32(Vs);

    {
        int r = tid >> 1, c0 = (tid & 1) * 4;
        const char* g = (const char*)(base + (size_t)(q0 + r) * (3*D_MODEL));
        #pragma unroll
        for (int c = 0; c < 4; c++) {
            int ch = c0 + c;
            cp16(qs + sw128(r, ch), g + ch * 16);
        }
    }
    const int T = q0 / 64 + 2;

    {
        int r = tid >> 2, c0 = (tid & 3) * 2;
        const char* gk = (const char*)(base + 1024 + (size_t)r * (3*D_MODEL));
        const char* gv = (const char*)(base + 2048 + (size_t)r * (3*D_MODEL));
        #pragma unroll
        for (int c = 0; c < 2; c++) {
            int ch = c0 + c;
            uint32_t sw = sw128(r, ch);
            cp16(ksm + sw, gk + ch * 16);
            cp16(vsm + sw, gv + ch * 16);
        }
    }
    cp_commit();
    cp_wait0();
    __syncthreads();

    uint32_t aq[4][4];
    {
        int row = wid * 16 + (lane & 15);
        #pragma unroll
        for (int ks = 0; ks < 4; ks++) {
            int ch = 2 * ks + (lane >> 4);
            ldsm4(aq[ks], qs + sw128(row, ch));
        }
    }

    float acc_o[8][4];
    #pragma unroll
    for (int j = 0; j < 8; j++)
        #pragma unroll
        for (int i = 0; i < 4; i++) acc_o[j][i] = 0.f;
    float m_lo = -1e30f, m_hi = -1e30f, l_lo = 0.f, l_hi = 0.f;

    for (int t = 0; t < T; t++) {
        int buf = t & 1;
        if (t + 1 < T) {
            int r = tid >> 2, c0 = (tid & 3) * 2;
            const char* gk = (const char*)(base + 1024 + (size_t)((t+1)*64 + r) * (3*D_MODEL));
            const char* gv = (const char*)(base + 2048 + (size_t)((t+1)*64 + r) * (3*D_MODEL));
            uint32_t so = (uint32_t)(buf ^ 1) * 8192;
            #pragma unroll
            for (int c = 0; c < 2; c++) {
                int ch = c0 + c;
                uint32_t sw = so + sw128(r, ch);
                cp16(ksm + sw, gk + ch * 16);
                cp16(vsm + sw, gv + ch * 16);
            }
            cp_commit();
            cp_wait1();
        } else {
            cp_wait0();
        }
        __syncthreads();

        uint32_t kb = ksm + buf * 8192;
        uint32_t vb = vsm + buf * 8192;

        float s[8][4];
        #pragma unroll
        for (int j = 0; j < 8; j++)
            #pragma unroll
            for (int i = 0; i < 4; i++) s[j][i] = 0.f;
        #pragma unroll
        for (int ks = 0; ks < 4; ks++) {
            #pragma unroll
            for (int j = 0; j < 8; j += 2) {
                int row = j * 8 + ((lane >> 4) << 3) + (lane & 7);
                int ch = 2 * ks + ((lane >> 3) & 1);
                uint32_t bk[4];
                ldsm4(bk, kb + sw128(row, ch));
                mma16816(s[j],     aq[ks], bk[0], bk[1]);
                mma16816(s[j + 1], aq[ks], bk[2], bk[3]);
            }
        }

        float mx_lo = -1e30f, mx_hi = -1e30f;
        if (t >= T - 2) {
            int q_lo = q0 + wid * 16 + (lane >> 2);
            int kvb  = t * 64 + (lane & 3) * 2;
            #pragma unroll
            for (int j = 0; j < 8; j++) {
                #pragma unroll
                for (int c = 0; c < 4; c++) {
                    int kv = kvb + j * 8 + (c & 1);
                    int qr = q_lo + ((c >= 2) ? 8 : 0);
                    if (kv > qr) s[j][c] = -1e30f;
                }
                mx_lo = fmaxf(mx_lo, fmaxf(s[j][0], s[j][1]));
                mx_hi = fmaxf(mx_hi, fmaxf(s[j][2], s[j][3]));
            }
        } else {
            #pragma unroll
            for (int j = 0; j < 8; j++) {
                mx_lo = fmaxf(mx_lo, fmaxf(s[j][0], s[j][1]));
                mx_hi = fmaxf(mx_hi, fmaxf(s[j][2], s[j][3]));
            }
        }
        mx_lo = fmaxf(mx_lo, __shfl_xor_sync(0xffffffffu, mx_lo, 1));
        mx_lo = fmaxf(mx_lo, __shfl_xor_sync(0xffffffffu, mx_lo, 2));
        mx_hi = fmaxf(mx_hi, __shfl_xor_sync(0xffffffffu, mx_hi, 1));
        mx_hi = fmaxf(mx_hi, __shfl_xor_sync(0xffffffffu, mx_hi, 2));

        float mn_lo = fmaxf(m_lo, mx_lo), mn_hi = fmaxf(m_hi, mx_hi);
        float cr_lo = ex2(m_lo - mn_lo), cr_hi = ex2(m_hi - mn_hi);
        m_lo = mn_lo; m_hi = mn_hi;

        float pl = 0.f, ph = 0.f;
        #pragma unroll
        for (int j = 0; j < 8; j++) {
            s[j][0] = ex2(s[j][0] - mn_lo); pl += s[j][0];
            s[j][1] = ex2(s[j][1] - mn_lo); pl += s[j][1];
            s[j][2] = ex2(s[j][2] - mn_hi); ph += s[j][2];
            s[j][3] = ex2(s[j][3] - mn_hi); ph += s[j][3];
        }
        pl += __shfl_xor_sync(0xffffffffu, pl, 1);
        pl += __shfl_xor_sync(0xffffffffu, pl, 2);
        ph += __shfl_xor_sync(0xffffffffu, ph, 1);
        ph += __shfl_xor_sync(0xffffffffu, ph, 2);
        l_lo = l_lo * cr_lo + pl;
        l_hi = l_hi * cr_hi + ph;

        #pragma unroll
        for (int j = 0; j < 8; j++) {
            acc_o[j][0] *= cr_lo; acc_o[j][1] *= cr_lo;
            acc_o[j][2] *= cr_hi; acc_o[j][3] *= cr_hi;
        }

        uint32_t ap[4][4];
        #pragma unroll
        for (int c16 = 0; c16 < 4; c16++) {
            ap[c16][0] = pack_h2(s[2*c16][0],   s[2*c16][1]);
            ap[c16][1] = pack_h2(s[2*c16][2],   s[2*c16][3]);
            ap[c16][2] = pack_h2(s[2*c16+1][0], s[2*c16+1][1]);
            ap[c16][3] = pack_h2(s[2*c16+1][2], s[2*c16+1][3]);
        }

        #pragma unroll
        for (int c16 = 0; c16 < 4; c16++) {
            int row = c16 * 16 + (lane & 15);
            #pragma unroll
            for (int j = 0; j < 8; j += 2) {
                int ch = j + (lane >> 4);
                uint32_t bv[4];
                ldsm4t(bv, vb + sw128(row, ch));
                mma16816(acc_o[j],     ap[c16], bv[0], bv[1]);
                mma16816(acc_o[j + 1], ap[c16], bv[2], bv[3]);
            }
        }
        __syncthreads();
    }

    float il_lo = 1.f / l_lo, il_hi = 1.f / l_hi;
    int r = lane >> 2, c = (lane & 3) * 2;
    __half* o_lo = out + (size_t)((b*SEQL) + q0 + wid*16 + r) * D_MODEL + h * 64 + c;
    __half* o_hi = o_lo + (size_t)8 * D_MODEL;
    #pragma unroll
    for (int j = 0; j < 8; j++) {
        *(uint32_t*)(o_lo + j*8) = pack_h2(acc_o[j][0]*il_lo, acc_o[j][1]*il_lo);
        *(uint32_t*)(o_hi + j*8) = pack_h2(acc_o[j][2]*il_hi, acc_o[j][3]*il_hi);
    }
}

// ---------------- weight converts ----------------
__global__ void f2h_one(const float* __restrict__ x, __half* __restrict__ y, int n4) {
    int i = blockIdx.x * blockDim.x + threadIdx.x;
    if (i < n4) {
        float4 v = ((const float4*)x)[i];
        ((uint2*)y)[i] = make_uint2(pack_h2(v.x, v.y), pack_h2(v.z, v.w));
    }
}

__global__ void f2h_rest(const float* __restrict__ wo, const float* __restrict__ w1,
                         const float* __restrict__ w3, const float* __restrict__ w2,
                         __half* __restrict__ y) {   // y = wh + o_wo
    const int n0 = D_MODEL*D_MODEL/4;
    const int n1 = n0 + DFF*D_MODEL/4;
    const int n2 = n1 + DFF*D_MODEL/4;
    const int n3 = n2 + D_MODEL*DFF/4;
    int i = blockIdx.x * blockDim.x + threadIdx.x;
    if (i >= n3) return;
    const float* src;
    int base;
    if      (i < n0) { src = wo; base = 0;  }
    else if (i < n1) { src = w1; base = n0; }
    else if (i < n2) { src = w3; base = n1; }
    else             { src = w2; base = n2; }
    float4 v = ((const float4*)src)[i - base];
    ((uint2*)y)[i] = make_uint2(pack_h2(v.x, v.y), pack_h2(v.z, v.w));
}

// ---------------- RMSNorm -> fp16 ----------------
__global__ void rmsnorm_k(const float* __restrict__ x, const float* __restrict__ g,
                          __half* __restrict__ out) {
    int row = blockIdx.x;
    const float4* x4 = (const float4*)(x + (size_t)row * D_MODEL);
    const float4* g4 = (const float4*)g;
    float4 v = x4[threadIdx.x];
    float ss = v.x*v.x + v.y*v.y + v.z*v.z + v.w*v.w;
    #pragma unroll
    for (int o = 16; o; o >>= 1) ss += __shfl_xor_sync(0xffffffffu, ss, o);
    __shared__ float wsum[8];
    int w = threadIdx.x >> 5, l = threadIdx.x & 31;
    if (l == 0) wsum[w] = ss;
    __syncthreads();
    if (w == 0) {
        float t = (l < 8) ? wsum[l] : 0.f;
        #pragma unroll
        for (int o = 4; o; o >>= 1) t += __shfl_xor_sync(0xffffffffu, t, o);
        if (l == 0) wsum[0] = t;
    }
    __syncthreads();
    float inv = rsqrtf(wsum[0] * (1.0f / (float)D_MODEL) + 1e-5f);
    float4 gg = g4[threadIdx.x];
    ((uint2*)(out + (size_t)row * D_MODEL))[threadIdx.x] =
        make_uint2(pack_h2(v.x*gg.x*inv, v.y*gg.y*inv), pack_h2(v.z*gg.z*inv, v.w*gg.w*inv));
}

// ---------------- launch ----------------
extern "C" void kernel_launch(void* const* d_in, const int* in_sizes, int n_in,
                              void* d_out, int out_size) {
    const float* x    = (const float*)d_in[0];
    const float* wqkv = (const float*)d_in[1];
    const float* wo   = (const float*)d_in[2];
    const float* g1   = (const float*)d_in[3];
    const float* g2   = (const float*)d_in[4];
    const float* w1   = (const float*)d_in[5];
    const float* w2   = (const float*)d_in[6];
    const float* w3   = (const float*)d_in[7];
    float* out = (float*)d_out;

    __half *xnh, *qkvh, *attnh, *ffhh, *wh;
    cudaGetSymbolAddress((void**)&xnh,   g_xnh);
    cudaGetSymbolAddress((void**)&qkvh,  g_qkvh);
    cudaGetSymbolAddress((void**)&attnh, g_attnh);
    cudaGetSymbolAddress((void**)&ffhh,  g_ffhh);
    cudaGetSymbolAddress((void**)&wh,    g_wh);

    size_t o_qkv = 0;
    size_t o_wo  = o_qkv + (size_t)3*D_MODEL*D_MODEL;
    size_t o_w1  = o_wo  + (size_t)D_MODEL*D_MODEL;
    size_t o_w3  = o_w1  + (size_t)DFF*D_MODEL;
    size_t o_w2  = o_w3  + (size_t)DFF*D_MODEL;

    // side stream: convert wo/w1/w3/w2 concurrently with the attention phase
    cudaStream_t s2;
    cudaStreamCreate(&s2);
    cudaEvent_t eFork, eW;
    cudaEventCreateWithFlags(&eFork, cudaEventDisableTiming);
    cudaEventCreateWithFlags(&eW,    cudaEventDisableTiming);

    cudaEventRecord(eFork, 0);
    cudaStreamWaitEvent(s2, eFork, 0);
    {
        int nr4 = (D_MODEL*D_MODEL + 2*DFF*D_MODEL + D_MODEL*DFF) / 4;
        f2h_rest<<<(nr4 + 255)/256, 256, 0, s2>>>(wo, w1, w3, w2, wh + o_wo);
    }
    cudaEventRecord(eW, s2);

    // main stream: wqkv convert -> rms -> qkv GEMM -> attention
    int nq4 = 3*D_MODEL*D_MODEL/4;
    f2h_one<<<(nq4 + 255)/256, 256>>>(wqkv, wh + o_qkv, nq4);
    rmsnorm_k<<<M_ROWS, 256>>>(x, g1, xnh);
    gemm_hmma<true><<<dim3(3*D_MODEL/GBN, M_ROWS/GBM), 256>>>(
        xnh, wh + o_qkv, nullptr, qkvh, M_ROWS, 3*D_MODEL, D_MODEL,
        QSCALE_LOG2, D_MODEL);
    attn_hmma<<<dim3(SEQL/128, BATCH*NH), 256>>>(qkvh, attnh);

    // join: remaining weights must be converted before the wo GEMM
    cudaStreamWaitEvent(0, eW, 0);
    gemm_hmma<false><<<dim3(D_MODEL/GBN, M_ROWS/GBM), 256>>>(
        attnh, wh + o_wo, x, out, M_ROWS, D_MODEL, D_MODEL, 1.f, 0);

    // out += W2 * swiglu(rmsnorm(out,g2))
    rmsnorm_k<<<M_ROWS, 256>>>(out, g2, xnh);
    gemm_ffup<<<dim3(DFF/GBN, M_ROWS/GBM), 256>>>(
        xnh, wh + o_w1, wh + o_w3, ffhh, M_ROWS, DFF, D_MODEL);
    gemm_hmma<false><<<dim3(D_MODEL/GBN, M_ROWS/GBM), 256>>>(
        ffhh, wh + o_w2, out, out, M_ROWS, D_MODEL, DFF, 1.f, 0);
}

// round 17
// speedup vs baseline: 1.1520x; 1.0754x over previous
#include <cuda_runtime.h>
#include <cuda_fp16.h>
#include <cstdint>
#include <math.h>

#define D_MODEL 1024
#define NH      16
#define DFF     2688
#define BATCH   2
#define SEQL    2048
#define M_ROWS  (BATCH*SEQL)   // 4096

// 0.125 (1/sqrt(64)) * log2(e): folded into Q at qkv-GEMM epilogue
#define QSCALE_LOG2 0.18033688f

// ---------------- scratch (device globals; no allocation APIs) ----------------
__device__ __half g_xnh [(size_t)M_ROWS*D_MODEL];
__device__ __half g_qkvh[(size_t)M_ROWS*3*D_MODEL];
__device__ __half g_attnh[(size_t)M_ROWS*D_MODEL];
__device__ __half g_ffhh[(size_t)M_ROWS*DFF];

#define W_TOTAL (3*D_MODEL*D_MODEL + D_MODEL*D_MODEL + 2*DFF*D_MODEL + D_MODEL*DFF)
__device__ __half g_wh[(size_t)W_TOTAL];

// ---------------- helpers ----------------
__device__ __forceinline__ uint32_t smem_u32(const void* p) {
    uint32_t a;
    asm("{ .reg .u64 t; cvta.to.shared.u64 t, %1; cvt.u32.u64 %0, t; }" : "=r"(a) : "l"(p));
    return a;
}
__device__ __forceinline__ void cp16(uint32_t saddr, const void* g) {
    asm volatile("cp.async.cg.shared.global [%0], [%1], 16;" :: "r"(saddr), "l"(g));
}
__device__ __forceinline__ void cp_commit() {
    asm volatile("cp.async.commit_group;" ::: "memory");
}
__device__ __forceinline__ void cp_wait0() {
    asm volatile("cp.async.wait_group 0;" ::: "memory");
}
__device__ __forceinline__ void cp_wait1() {
    asm volatile("cp.async.wait_group 1;" ::: "memory");
}
__device__ __forceinline__ void ldsm4(uint32_t* r, uint32_t saddr) {
    asm volatile("ldmatrix.sync.aligned.m8n8.x4.shared.b16 {%0,%1,%2,%3}, [%4];"
        : "=r"(r[0]), "=r"(r[1]), "=r"(r[2]), "=r"(r[3]) : "r"(saddr));
}
__device__ __forceinline__ void ldsm4t(uint32_t* r, uint32_t saddr) {
    asm volatile("ldmatrix.sync.aligned.m8n8.x4.trans.shared.b16 {%0,%1,%2,%3}, [%4];"
        : "=r"(r[0]), "=r"(r[1]), "=r"(r[2]), "=r"(r[3]) : "r"(saddr));
}
__device__ __forceinline__ void mma16816(float* c, const uint32_t* a, uint32_t b0, uint32_t b1) {
    asm volatile(
        "mma.sync.aligned.m16n8k16.row.col.f32.f16.f16.f32 "
        "{%0,%1,%2,%3}, {%4,%5,%6,%7}, {%8,%9}, {%0,%1,%2,%3};"
        : "+f"(c[0]), "+f"(c[1]), "+f"(c[2]), "+f"(c[3])
        : "r"(a[0]), "r"(a[1]), "r"(a[2]), "r"(a[3]), "r"(b0), "r"(b1));
}
__device__ __forceinline__ uint32_t pack_h2(float a, float b) {
    __half2 h = __floats2half2_rn(a, b);
    return *(uint32_t*)&h;
}
__device__ __forceinline__ float ex2(float x) {
    float r;
    asm("ex2.approx.f32 %0, %1;" : "=f"(r) : "f"(x));
    return r;
}
// 64B-row swizzle (BK=32 tiles)
__device__ __forceinline__ uint32_t sw_off(int row, int chunk) {
    return (uint32_t)(row * 64 + ((chunk ^ ((row >> 1) & 3)) << 4));
}
// 128B-row swizzle (64-col fp16 tiles)
__device__ __forceinline__ uint32_t sw128(int row, int chunk) {
    return (uint32_t)(row * 128 + ((chunk ^ (row & 7)) << 4));
}
__device__ __forceinline__ float silu_mul(float a, float b) {
    return a * (1.f / (1.f + __expf(-a))) * b;
}

// ---------------- HMMA GEMM (R14-proven): C = A*B^T (+resid) ----------------
// CTA 64x128, 256 threads (8 warps: 2m x 4n), warp tile 32x32, BK=32, 2-stage.
// __launch_bounds__(256,3) -> ~78 regs, 3 CTAs / 24 warps per SM (measured best).
#define GBM 64
#define GBN 128
#define BK 32
#define A_TB 4096
#define B_TB 8192

template<bool OUT_HALF>
__global__ void __launch_bounds__(256, 3) gemm_hmma(
    const __half* __restrict__ A, const __half* __restrict__ B,
    const float* __restrict__ resid, void* __restrict__ Cv,
    int M, int N, int K, float oscale, int oscale_cols)
{
    __shared__ __align__(128) __half As[2][GBM*BK];
    __shared__ __align__(128) __half Bs[2][GBN*BK];

    int tid = threadIdx.x;
    int wid = tid >> 5, lane = tid & 31;
    int wm = wid & 1, wn = wid >> 1;
    int m0 = blockIdx.y * GBM, n0 = blockIdx.x * GBN;

    uint32_t as_base = smem_u32(As);
    uint32_t bs_base = smem_u32(Bs);

    int ar = tid >> 2, ac = tid & 3;
    const char* gA = (const char*)(A + (size_t)(m0 + ar) * K) + ac * 16;
    uint32_t sA = as_base + sw_off(ar, ac);
    int br = tid >> 1, bc = (tid & 1) * 2;
    const char* gB = (const char*)(B + (size_t)(n0 + br) * K) + bc * 16;
    uint32_t sB0 = bs_base + sw_off(br, bc);
    uint32_t sB1 = bs_base + sw_off(br, bc + 1);

    int rowsel = ((lane >> 3) & 1) * 8 + (lane & 7);
    int chunk_hi = lane >> 4;

    float acc[2][4][4];
    #pragma unroll
    for (int mt = 0; mt < 2; mt++)
        #pragma unroll
        for (int nt = 0; nt < 4; nt++)
            #pragma unroll
            for (int i = 0; i < 4; i++) acc[mt][nt][i] = 0.f;

    int iters = K / BK;
    cp16(sA, gA);
    cp16(sB0, gB); cp16(sB1, gB + 16);
    cp_commit();
    cp_wait0();
    __syncthreads();

    int buf = 0;
    for (int kb = 0; kb < iters; kb++) {
        if (kb + 1 < iters) {
            size_t go = (size_t)(kb + 1) * 64;
            cp16(sA + (buf ^ 1) * A_TB, gA + go);
            cp16(sB0 + (buf ^ 1) * B_TB, gB + go);
            cp16(sB1 + (buf ^ 1) * B_TB, gB + go + 16);
            cp_commit();
        }
        uint32_t ab = as_base + buf * A_TB;
        uint32_t bb = bs_base + buf * B_TB;
        #pragma unroll
        for (int ks = 0; ks < 2; ks++) {
            int cb = ks * 2 + chunk_hi;
            uint32_t a[2][4];
            #pragma unroll
            for (int mt = 0; mt < 2; mt++)
                ldsm4(a[mt], ab + sw_off(wm * 32 + mt * 16 + rowsel, cb));
            uint32_t b[2][4];
            #pragma unroll
            for (int p = 0; p < 2; p++)
                ldsm4(b[p], bb + sw_off(wn * 32 + p * 16 + rowsel, cb));
            #pragma unroll
            for (int mt = 0; mt < 2; mt++)
                #pragma unroll
                for (int p = 0; p < 2; p++)
                    #pragma unroll
                    for (int q = 0; q < 2; q++)
                        mma16816(acc[mt][p*2+q], a[mt], b[p][q], b[p][2 + q]);
        }
        if (kb + 1 < iters) cp_wait0();
        __syncthreads();
        buf ^= 1;
    }

    int r0 = lane >> 2, c0 = (lane & 3) * 2;
    #pragma unroll
    for (int mt = 0; mt < 2; mt++) {
        #pragma unroll
        for (int nt = 0; nt < 4; nt++) {
            int row = m0 + wm * 32 + mt * 16 + r0;
            int col = n0 + wn * 32 + nt * 8 + c0;
            if (OUT_HALF) {
                float sc = (col < oscale_cols) ? oscale : 1.f;
                __half* C = (__half*)Cv;
                *(uint32_t*)(C + (size_t)row * N + col)       = pack_h2(acc[mt][nt][0]*sc, acc[mt][nt][1]*sc);
                *(uint32_t*)(C + (size_t)(row + 8) * N + col) = pack_h2(acc[mt][nt][2]*sc, acc[mt][nt][3]*sc);
            } else {
                float* C = (float*)Cv;
                float2 v0 = make_float2(acc[mt][nt][0], acc[mt][nt][1]);
                float2 v1 = make_float2(acc[mt][nt][2], acc[mt][nt][3]);
                if (resid) {
                    float2 a0 = *(const float2*)(resid + (size_t)row * N + col);
                    float2 a1 = *(const float2*)(resid + (size_t)(row + 8) * N + col);
                    v0.x += a0.x; v0.y += a0.y; v1.x += a1.x; v1.y += a1.y;
                }
                *(float2*)(C + (size_t)row * N + col)       = v0;
                *(float2*)(C + (size_t)(row + 8) * N + col) = v1;
            }
        }
    }
}

// ---------------- Fused FFN-up: H = silu(A*W1^T)*(A*W3^T) ----------------
// Occupancy step 2: CTA 64x64, 8 warps (2m x 4n), dual 32x16 warp tiles,
// BK=32, 2-stage. ~70 regs -> 3 CTAs / 24 warps per SM.
#define FBN 64
#define F_TB 4096   // 64 rows x 64B per stage (A and each B)

__global__ void __launch_bounds__(256, 3) gemm_ffup(
    const __half* __restrict__ A, const __half* __restrict__ B1,
    const __half* __restrict__ B2, __half* __restrict__ H,
    int M, int N, int K)
{
    __shared__ __align__(128) __half As [2][GBM*BK];
    __shared__ __align__(128) __half B1s[2][FBN*BK];
    __shared__ __align__(128) __half B2s[2][FBN*BK];

    int tid = threadIdx.x;
    int wid = tid >> 5, lane = tid & 31;
    int wm = wid & 1, wn = wid >> 1;     // 2m x 4n, warp tile 32x16 (dual)
    int m0 = blockIdx.y * GBM, n0 = blockIdx.x * FBN;

    uint32_t as_base = smem_u32(As);
    uint32_t b1_base = smem_u32(B1s);
    uint32_t b2_base = smem_u32(B2s);

    // all three loaders: 64 rows x 4 chunks, 1 cp16/thread each
    int ar = tid >> 2, ac = tid & 3;
    const char* gA  = (const char*)(A  + (size_t)(m0 + ar) * K) + ac * 16;
    const char* gB1 = (const char*)(B1 + (size_t)(n0 + ar) * K) + ac * 16;
    const char* gB2 = (const char*)(B2 + (size_t)(n0 + ar) * K) + ac * 16;
    uint32_t so = sw_off(ar, ac);

    int rowsel = ((lane >> 3) & 1) * 8 + (lane & 7);
    int chunk_hi = lane >> 4;

    float acc1[2][2][4], acc2[2][2][4];
    #pragma unroll
    for (int mt = 0; mt < 2; mt++)
        #pragma unroll
        for (int nt = 0; nt < 2; nt++)
            #pragma unroll
            for (int i = 0; i < 4; i++) { acc1[mt][nt][i] = 0.f; acc2[mt][nt][i] = 0.f; }

    int iters = K / BK;
    cp16(as_base + so, gA);
    cp16(b1_base + so, gB1);
    cp16(b2_base + so, gB2);
    cp_commit();
    cp_wait0();
    __syncthreads();

    int buf = 0;
    for (int kb = 0; kb < iters; kb++) {
        if (kb + 1 < iters) {
            size_t go = (size_t)(kb + 1) * 64;
            uint32_t bo = (buf ^ 1) * F_TB;
            cp16(as_base + bo + so, gA + go);
            cp16(b1_base + bo + so, gB1 + go);
            cp16(b2_base + bo + so, gB2 + go);
            cp_commit();
        }
        uint32_t ab  = as_base + buf * F_TB;
        uint32_t bb1 = b1_base + buf * F_TB;
        uint32_t bb2 = b2_base + buf * F_TB;
        #pragma unroll
        for (int ks = 0; ks < 2; ks++) {
            int cb = ks * 2 + chunk_hi;
            uint32_t a[2][4];
            #pragma unroll
            for (int mt = 0; mt < 2; mt++)
                ldsm4(a[mt], ab + sw_off(wm * 32 + mt * 16 + rowsel, cb));
            uint32_t b1[4], b2[4];
            uint32_t ro = sw_off(wn * 16 + rowsel, cb);
            ldsm4(b1, bb1 + ro);
            ldsm4(b2, bb2 + ro);
            #pragma unroll
            for (int mt = 0; mt < 2; mt++)
                #pragma unroll
                for (int q = 0; q < 2; q++) {
                    mma16816(acc1[mt][q], a[mt], b1[q], b1[2 + q]);
                    mma16816(acc2[mt][q], a[mt], b2[q], b2[2 + q]);
                }
        }
        if (kb + 1 < iters) cp_wait0();
        __syncthreads();
        buf ^= 1;
    }

    const int r0 = lane >> 2, c0 = (lane & 3) * 2;
    #pragma unroll
    for (int mt = 0; mt < 2; mt++) {
        #pragma unroll
        for (int nt = 0; nt < 2; nt++) {
            int row = m0 + wm * 32 + mt * 16 + r0;
            int col = n0 + wn * 16 + nt * 8 + c0;
            float h0 = silu_mul(acc1[mt][nt][0], acc2[mt][nt][0]);
            float h1 = silu_mul(acc1[mt][nt][1], acc2[mt][nt][1]);
            float h2 = silu_mul(acc1[mt][nt][2], acc2[mt][nt][2]);
            float h3 = silu_mul(acc1[mt][nt][3], acc2[mt][nt][3]);
            *(uint32_t*)(H + (size_t)row * N + col)       = pack_h2(h0, h1);
            *(uint32_t*)(H + (size_t)(row + 8) * N + col) = pack_h2(h2, h3);
        }
    }
}

// ---------------- HMMA flash attention (log2-domain softmax; Q pre-scaled) ----------------
__global__ void __launch_bounds__(256) attn_hmma(const __half* __restrict__ qkv,
                                                 __half* __restrict__ out) {
    __shared__ __align__(128) __half Qs[128*64];
    __shared__ __align__(128) __half Ks[2][64*64];
    __shared__ __align__(128) __half Vs[2][64*64];
    const int tid = threadIdx.x, lane = tid & 31, wid = tid >> 5;
    const int b = blockIdx.y >> 4, h = blockIdx.y & 15;
    const int q0 = ((int)gridDim.x - 1 - (int)blockIdx.x) * 128;
    const __half* base = qkv + (size_t)b * SEQL * (3*D_MODEL) + h * 64;

    uint32_t qs  = smem_u32(Qs);
    uint32_t ksm = smem_u32(Ks);
    uint32_t vsm = smem_u32(Vs);

    {
        int r = tid >> 1, c0 = (tid & 1) * 4;
        const char* g = (const char*)(base + (size_t)(q0 + r) * (3*D_MODEL));
        #pragma unroll
        for (int c = 0; c < 4; c++) {
            int ch = c0 + c;
            cp16(qs + sw128(r, ch), g + ch * 16);
        }
    }
    const int T = q0 / 64 + 2;

    {
        int r = tid >> 2, c0 = (tid & 3) * 2;
        const char* gk = (const char*)(base + 1024 + (size_t)r * (3*D_MODEL));
        const char* gv = (const char*)(base + 2048 + (size_t)r * (3*D_MODEL));
        #pragma unroll
        for (int c = 0; c < 2; c++) {
            int ch = c0 + c;
            uint32_t sw = sw128(r, ch);
            cp16(ksm + sw, gk + ch * 16);
            cp16(vsm + sw, gv + ch * 16);
        }
    }
    cp_commit();
    cp_wait0();
    __syncthreads();

    uint32_t aq[4][4];
    {
        int row = wid * 16 + (lane & 15);
        #pragma unroll
        for (int ks = 0; ks < 4; ks++) {
            int ch = 2 * ks + (lane >> 4);
            ldsm4(aq[ks], qs + sw128(row, ch));
        }
    }

    float acc_o[8][4];
    #pragma unroll
    for (int j = 0; j < 8; j++)
        #pragma unroll
        for (int i = 0; i < 4; i++) acc_o[j][i] = 0.f;
    float m_lo = -1e30f, m_hi = -1e30f, l_lo = 0.f, l_hi = 0.f;

    for (int t = 0; t < T; t++) {
        int buf = t & 1;
        if (t + 1 < T) {
            int r = tid >> 2, c0 = (tid & 3) * 2;
            const char* gk = (const char*)(base + 1024 + (size_t)((t+1)*64 + r) * (3*D_MODEL));
            const char* gv = (const char*)(base + 2048 + (size_t)((t+1)*64 + r) * (3*D_MODEL));
            uint32_t so = (uint32_t)(buf ^ 1) * 8192;
            #pragma unroll
            for (int c = 0; c < 2; c++) {
                int ch = c0 + c;
                uint32_t sw = so + sw128(r, ch);
                cp16(ksm + sw, gk + ch * 16);
                cp16(vsm + sw, gv + ch * 16);
            }
            cp_commit();
            cp_wait1();
        } else {
            cp_wait0();
        }
        __syncthreads();

        uint32_t kb = ksm + buf * 8192;
        uint32_t vb = vsm + buf * 8192;

        float s[8][4];
        #pragma unroll
        for (int j = 0; j < 8; j++)
            #pragma unroll
            for (int i = 0; i < 4; i++) s[j][i] = 0.f;
        #pragma unroll
        for (int ks = 0; ks < 4; ks++) {
            #pragma unroll
            for (int j = 0; j < 8; j += 2) {
                int row = j * 8 + ((lane >> 4) << 3) + (lane & 7);
                int ch = 2 * ks + ((lane >> 3) & 1);
                uint32_t bk[4];
                ldsm4(bk, kb + sw128(row, ch));
                mma16816(s[j],     aq[ks], bk[0], bk[1]);
                mma16816(s[j + 1], aq[ks], bk[2], bk[3]);
            }
        }

        float mx_lo = -1e30f, mx_hi = -1e30f;
        if (t >= T - 2) {
            int q_lo = q0 + wid * 16 + (lane >> 2);
            int kvb  = t * 64 + (lane & 3) * 2;
            #pragma unroll
            for (int j = 0; j < 8; j++) {
                #pragma unroll
                for (int c = 0; c < 4; c++) {
                    int kv = kvb + j * 8 + (c & 1);
                    int qr = q_lo + ((c >= 2) ? 8 : 0);
                    if (kv > qr) s[j][c] = -1e30f;
                }
                mx_lo = fmaxf(mx_lo, fmaxf(s[j][0], s[j][1]));
                mx_hi = fmaxf(mx_hi, fmaxf(s[j][2], s[j][3]));
            }
        } else {
            #pragma unroll
            for (int j = 0; j < 8; j++) {
                mx_lo = fmaxf(mx_lo, fmaxf(s[j][0], s[j][1]));
                mx_hi = fmaxf(mx_hi, fmaxf(s[j][2], s[j][3]));
            }
        }
        mx_lo = fmaxf(mx_lo, __shfl_xor_sync(0xffffffffu, mx_lo, 1));
        mx_lo = fmaxf(mx_lo, __shfl_xor_sync(0xffffffffu, mx_lo, 2));
        mx_hi = fmaxf(mx_hi, __shfl_xor_sync(0xffffffffu, mx_hi, 1));
        mx_hi = fmaxf(mx_hi, __shfl_xor_sync(0xffffffffu, mx_hi, 2));

        float mn_lo = fmaxf(m_lo, mx_lo), mn_hi = fmaxf(m_hi, mx_hi);
        float cr_lo = ex2(m_lo - mn_lo), cr_hi = ex2(m_hi - mn_hi);
        m_lo = mn_lo; m_hi = mn_hi;

        float pl = 0.f, ph = 0.f;
        #pragma unroll
        for (int j = 0; j < 8; j++) {
            s[j][0] = ex2(s[j][0] - mn_lo); pl += s[j][0];
            s[j][1] = ex2(s[j][1] - mn_lo); pl += s[j][1];
            s[j][2] = ex2(s[j][2] - mn_hi); ph += s[j][2];
            s[j][3] = ex2(s[j][3] - mn_hi); ph += s[j][3];
        }
        pl += __shfl_xor_sync(0xffffffffu, pl, 1);
        pl += __shfl_xor_sync(0xffffffffu, pl, 2);
        ph += __shfl_xor_sync(0xffffffffu, ph, 1);
        ph += __shfl_xor_sync(0xffffffffu, ph, 2);
        l_lo = l_lo * cr_lo + pl;
        l_hi = l_hi * cr_hi + ph;

        #pragma unroll
        for (int j = 0; j < 8; j++) {
            acc_o[j][0] *= cr_lo; acc_o[j][1] *= cr_lo;
            acc_o[j][2] *= cr_hi; acc_o[j][3] *= cr_hi;
        }

        uint32_t ap[4][4];
        #pragma unroll
        for (int c16 = 0; c16 < 4; c16++) {
            ap[c16][0] = pack_h2(s[2*c16][0],   s[2*c16][1]);
            ap[c16][1] = pack_h2(s[2*c16][2],   s[2*c16][3]);
            ap[c16][2] = pack_h2(s[2*c16+1][0], s[2*c16+1][1]);
            ap[c16][3] = pack_h2(s[2*c16+1][2], s[2*c16+1][3]);
        }

        #pragma unroll
        for (int c16 = 0; c16 < 4; c16++) {
            int row = c16 * 16 + (lane & 15);
            #pragma unroll
            for (int j = 0; j < 8; j += 2) {
                int ch = j + (lane >> 4);
                uint32_t bv[4];
                ldsm4t(bv, vb + sw128(row, ch));
                mma16816(acc_o[j],     ap[c16], bv[0], bv[1]);
                mma16816(acc_o[j + 1], ap[c16], bv[2], bv[3]);
            }
        }
        __syncthreads();
    }

    float il_lo = 1.f / l_lo, il_hi = 1.f / l_hi;
    int r = lane >> 2, c = (lane & 3) * 2;
    __half* o_lo = out + (size_t)((b*SEQL) + q0 + wid*16 + r) * D_MODEL + h * 64 + c;
    __half* o_hi = o_lo + (size_t)8 * D_MODEL;
    #pragma unroll
    for (int j = 0; j < 8; j++) {
        *(uint32_t*)(o_lo + j*8) = pack_h2(acc_o[j][0]*il_lo, acc_o[j][1]*il_lo);
        *(uint32_t*)(o_hi + j*8) = pack_h2(acc_o[j][2]*il_hi, acc_o[j][3]*il_hi);
    }
}

// ---------------- weight converts ----------------
__global__ void f2h_one(const float* __restrict__ x, __half* __restrict__ y, int n4) {
    int i = blockIdx.x * blockDim.x + threadIdx.x;
    if (i < n4) {
        float4 v = ((const float4*)x)[i];
        ((uint2*)y)[i] = make_uint2(pack_h2(v.x, v.y), pack_h2(v.z, v.w));
    }
}

__global__ void f2h_rest(const float* __restrict__ wo, const float* __restrict__ w1,
                         const float* __restrict__ w3, const float* __restrict__ w2,
                         __half* __restrict__ y) {   // y = wh + o_wo
    const int n0 = D_MODEL*D_MODEL/4;
    const int n1 = n0 + DFF*D_MODEL/4;
    const int n2 = n1 + DFF*D_MODEL/4;
    const int n3 = n2 + D_MODEL*DFF/4;
    int i = blockIdx.x * blockDim.x + threadIdx.x;
    if (i >= n3) return;
    const float* src;
    int base;
    if      (i < n0) { src = wo; base = 0;  }
    else if (i < n1) { src = w1; base = n0; }
    else if (i < n2) { src = w3; base = n1; }
    else             { src = w2; base = n2; }
    float4 v = ((const float4*)src)[i - base];
    ((uint2*)y)[i] = make_uint2(pack_h2(v.x, v.y), pack_h2(v.z, v.w));
}

// ---------------- RMSNorm -> fp16 ----------------
__global__ void rmsnorm_k(const float* __restrict__ x, const float* __restrict__ g,
                          __half* __restrict__ out) {
    int row = blockIdx.x;
    const float4* x4 = (const float4*)(x + (size_t)row * D_MODEL);
    const float4* g4 = (const float4*)g;
    float4 v = x4[threadIdx.x];
    float ss = v.x*v.x + v.y*v.y + v.z*v.z + v.w*v.w;
    #pragma unroll
    for (int o = 16; o; o >>= 1) ss += __shfl_xor_sync(0xffffffffu, ss, o);
    __shared__ float wsum[8];
    int w = threadIdx.x >> 5, l = threadIdx.x & 31;
    if (l == 0) wsum[w] = ss;
    __syncthreads();
    if (w == 0) {
        float t = (l < 8) ? wsum[l] : 0.f;
        #pragma unroll
        for (int o = 4; o; o >>= 1) t += __shfl_xor_sync(0xffffffffu, t, o);
        if (l == 0) wsum[0] = t;
    }
    __syncthreads();
    float inv = rsqrtf(wsum[0] * (1.0f / (float)D_MODEL) + 1e-5f);
    float4 gg = g4[threadIdx.x];
    ((uint2*)(out + (size_t)row * D_MODEL))[threadIdx.x] =
        make_uint2(pack_h2(v.x*gg.x*inv, v.y*gg.y*inv), pack_h2(v.z*gg.z*inv, v.w*gg.w*inv));
}

// ---------------- launch ----------------
extern "C" void kernel_launch(void* const* d_in, const int* in_sizes, int n_in,
                              void* d_out, int out_size) {
    const float* x    = (const float*)d_in[0];
    const float* wqkv = (const float*)d_in[1];
    const float* wo   = (const float*)d_in[2];
    const float* g1   = (const float*)d_in[3];
    const float* g2   = (const float*)d_in[4];
    const float* w1   = (const float*)d_in[5];
    const float* w2   = (const float*)d_in[6];
    const float* w3   = (const float*)d_in[7];
    float* out = (float*)d_out;

    __half *xnh, *qkvh, *attnh, *ffhh, *wh;
    cudaGetSymbolAddress((void**)&xnh,   g_xnh);
    cudaGetSymbolAddress((void**)&qkvh,  g_qkvh);
    cudaGetSymbolAddress((void**)&attnh, g_attnh);
    cudaGetSymbolAddress((void**)&ffhh,  g_ffhh);
    cudaGetSymbolAddress((void**)&wh,    g_wh);

    size_t o_qkv = 0;
    size_t o_wo  = o_qkv + (size_t)3*D_MODEL*D_MODEL;
    size_t o_w1  = o_wo  + (size_t)D_MODEL*D_MODEL;
    size_t o_w3  = o_w1  + (size_t)DFF*D_MODEL;
    size_t o_w2  = o_w3  + (size_t)DFF*D_MODEL;

    // side stream: convert wo/w1/w3/w2 concurrently with the attention phase
    cudaStream_t s2;
    cudaStreamCreate(&s2);
    cudaEvent_t eFork, eW;
    cudaEventCreateWithFlags(&eFork, cudaEventDisableTiming);
    cudaEventCreateWithFlags(&eW,    cudaEventDisableTiming);

    cudaEventRecord(eFork, 0);
    cudaStreamWaitEvent(s2, eFork, 0);
    {
        int nr4 = (D_MODEL*D_MODEL + 2*DFF*D_MODEL + D_MODEL*DFF) / 4;
        f2h_rest<<<(nr4 + 255)/256, 256, 0, s2>>>(wo, w1, w3, w2, wh + o_wo);
    }
    cudaEventRecord(eW, s2);

    // main stream: wqkv convert -> rms -> qkv GEMM -> attention
    int nq4 = 3*D_MODEL*D_MODEL/4;
    f2h_one<<<(nq4 + 255)/256, 256>>>(wqkv, wh + o_qkv, nq4);
    rmsnorm_k<<<M_ROWS, 256>>>(x, g1, xnh);
    gemm_hmma<true><<<dim3(3*D_MODEL/GBN, M_ROWS/GBM), 256>>>(
        xnh, wh + o_qkv, nullptr, qkvh, M_ROWS, 3*D_MODEL, D_MODEL,
        QSCALE_LOG2, D_MODEL);
    attn_hmma<<<dim3(SEQL/128, BATCH*NH), 256>>>(qkvh, attnh);

    // join: remaining weights must be converted before the wo GEMM
    cudaStreamWaitEvent(0, eW, 0);
    gemm_hmma<false><<<dim3(D_MODEL/GBN, M_ROWS/GBM), 256>>>(
        attnh, wh + o_wo, x, out, M_ROWS, D_MODEL, D_MODEL, 1.f, 0);

    // out += W2 * swiglu(rmsnorm(out,g2))
    rmsnorm_k<<<M_ROWS, 256>>>(out, g2, xnh);
    gemm_ffup<<<dim3(DFF/FBN, M_ROWS/GBM), 256>>>(
        xnh, wh + o_w1, wh + o_w3, ffhh, M_ROWS, DFF, D_MODEL);
    gemm_hmma<false><<<dim3(D_MODEL/GBN, M_ROWS/GBM), 256>>>(
        ffhh, wh + o_w2, out, out, M_ROWS, D_MODEL, DFF, 1.f, 0);
}